// round 16
// baseline (speedup 1.0000x reference)
#include <cuda_runtime.h>
#include <cuda_bf16.h>
#include <cstdint>

// ---------------- problem constants ----------------
#define BB   8
#define NR   4096
#define NK   20
#define FF   256
#define HH   4
#define KH   80
#define KNN  8

// ---------------- device scratch ----------------
__device__ float g_ftdst[BB * NK * 1024];
__device__ float g_V[BB * FF * KH];
__device__ float g_S[BB * NK * HH * 4];

// ---------------- helpers ----------------
__device__ __forceinline__ void split_pack(float f0, float f1, uint32_t& hi, uint32_t& lo) {
    uint32_t u0 = __float_as_uint(f0), u1 = __float_as_uint(f1);
    hi = (u1 & 0xFFFF0000u) | (u0 >> 16);
    float r0 = f0 - __uint_as_float(u0 & 0xFFFF0000u);
    float r1 = f1 - __uint_as_float(u1 & 0xFFFF0000u);
    asm("cvt.rn.bf16x2.f32 %0, %1, %2;" : "=r"(lo) : "f"(r1), "f"(r0));
}
__device__ __forceinline__ void mma16816(float* c, const uint32_t* a, uint32_t b0, uint32_t b1) {
    asm volatile(
        "mma.sync.aligned.m16n8k16.row.col.f32.bf16.bf16.f32 "
        "{%0,%1,%2,%3}, {%4,%5,%6,%7}, {%8,%9}, {%0,%1,%2,%3};"
        : "+f"(c[0]), "+f"(c[1]), "+f"(c[2]), "+f"(c[3])
        : "r"(a[0]), "r"(a[1]), "r"(a[2]), "r"(a[3]), "r"(b0), "r"(b1));
}

// ---------------- A1: ft_dst = h0_kp @ W_src (+ zero g_V, g_S) ----------------
#define FT_SMEM_FLOATS (NK * FF + 256 * 65)
__global__ void __launch_bounds__(256) k_ftdst(const float* __restrict__ h0,
                                               const float* __restrict__ W) {
    extern __shared__ float sm[];
    float* hs = sm;
    float* ws = sm + NK * FF;
    int b = blockIdx.y, ct = blockIdx.x;
    if (ct == 0) {
        for (int i = threadIdx.x; i < FF * KH; i += 256) g_V[b * FF * KH + i] = 0.f;
        for (int i = threadIdx.x; i < NK * HH * 4; i += 256) g_S[b * NK * HH * 4 + i] = 0.f;
    }
    for (int i = threadIdx.x; i < NK * FF; i += 256) hs[i] = h0[b * NK * FF + i];
#pragma unroll 8
    for (int i = threadIdx.x; i < 256 * 64; i += 256) {
        int f = i >> 6, c = i & 63;
        ws[f * 65 + c] = W[f * 1024 + ct * 64 + c];
    }
    __syncthreads();
    int cg = threadIdx.x & 63;
    int rgp = threadIdx.x >> 6;
    float acc[5] = {0.f, 0.f, 0.f, 0.f, 0.f};
#pragma unroll 8
    for (int f = 0; f < 256; f++) {
        float w = ws[f * 65 + cg];
#pragma unroll
        for (int q = 0; q < 5; q++) acc[q] += hs[(rgp * 5 + q) * 256 + f] * w;
    }
    int c = ct * 64 + cg;
#pragma unroll
    for (int q = 0; q < 5; q++)
        g_ftdst[(b * NK + rgp * 5 + q) * 1024 + c] = acc[q];
}

// ---------------- A2: V reduction ----------------
#define V_SMEM_FLOATS (64 * 257 + NK * 256)
__global__ void __launch_bounds__(256) k_V(const float* __restrict__ W) {
    extern __shared__ float sm[];
    float* ws2 = sm;
    float* fts2 = sm + 64 * 257;
    int b = blockIdx.y;
    int ft = blockIdx.x >> 2, ds = blockIdx.x & 3;
    int fbase = ft * 64, dbase = ds * 64;
#pragma unroll 4
    for (int i = threadIdx.x; i < 64 * 256; i += 256) {
        int fi = i >> 8, rest = i & 255;
        int h = rest >> 6, dd = rest & 63;
        ws2[fi * 257 + rest] = W[(fbase + fi) * 1024 + h * 256 + dbase + dd];
    }
#pragma unroll 4
    for (int i = threadIdx.x; i < NK * 256; i += 256) {
        int rest = i & 255;
        int h = rest >> 6, dd = rest & 63;
        int k = i >> 8;
        fts2[i] = g_ftdst[b * 20480 + k * 1024 + h * 256 + dbase + dd];
    }
    __syncthreads();
    int fi = threadIdx.x & 63;
    int h  = threadIdx.x >> 6;
    float acc[NK];
#pragma unroll
    for (int j = 0; j < NK; j++) acc[j] = 0.f;
    const float* wp = ws2 + fi * 257 + h * 64;
    const float* fp = fts2 + h * 64;
#pragma unroll 2
    for (int dd = 0; dd < 64; dd++) {
        float w = wp[dd];
#pragma unroll
        for (int j = 0; j < NK; j++) acc[j] += w * fp[j * 256 + dd];
    }
    float* gv = g_V + b * (FF * KH) + (fbase + fi) * KH + h;
#pragma unroll
    for (int j = 0; j < NK; j++)
        atomicAdd(gv + j * 4, acc[j] * 0.0625f);
}

// ---------------- B: HMMA attention ----------------
#define SM_BF   0
#define SM_XS   81920
#define SM_RED  (SM_XS + 4096)
#define ATTN_SMEM_BYTES (SM_RED + 20480)   // 106496
__global__ void __launch_bounds__(512, 1) k_attn(const float* __restrict__ h_rec,
                                                 const float* __restrict__ x_rec) {
    extern __shared__ char smc[];
    uint32_t* bf = (uint32_t*)(smc + SM_BF);
    float4* xs = (float4*)(smc + SM_XS);
    float* red = (float*)(smc + SM_RED);
    int b = blockIdx.y;
    int tid = threadIdx.x;
    int wid = tid >> 5, lane = tid & 31;
    int g = lane >> 2, tg = lane & 3;
    int rowbase = blockIdx.x * 256;

    {
        const float* gV = g_V + b * (FF * KH);
#pragma unroll
        for (int q = 0; q < 20; q++) {
            int i = tid + q * 512;
            int reg = i & 1;
            int l2 = (i >> 1) & 31;
            int knt = i >> 6;
            int nt = knt % 10, ks = knt / 10;
            int g2 = l2 >> 2, t2 = l2 & 3;
            int k = ks * 16 + 2 * t2 + reg * 8;
            int n = nt * 8 + g2;
            float v0 = __ldg(gV + k * 80 + n);
            float v1 = __ldg(gV + (k + 1) * 80 + n);
            uint32_t hi, lo;
            split_pack(v0, v1, hi, lo);
            bf[i] = hi;
            bf[10240 + i] = lo;
        }
    }
    if (tid < 256) {
        const float* xp = x_rec + ((size_t)(b * NR + rowbase + tid)) * 3;
        xs[tid] = make_float4(xp[0], xp[1], xp[2], 0.f);
    }
    __syncthreads();

    const float* hp0 = h_rec + ((size_t)(b * NR + rowbase + wid * 16 + g)) * FF;
    const float* hp1 = hp0 + 8 * FF;
    int cb = 2 * tg;
    float c[10][4];
#pragma unroll
    for (int nt = 0; nt < 10; nt++)
#pragma unroll
        for (int e = 0; e < 4; e++) c[nt][e] = 0.f;

    float2 pA[2][4];
#pragma unroll
    for (int s = 0; s < 2; s++) {
        pA[s][0] = *(const float2*)(hp0 + s * 16 + cb);
        pA[s][1] = *(const float2*)(hp1 + s * 16 + cb);
        pA[s][2] = *(const float2*)(hp0 + s * 16 + cb + 8);
        pA[s][3] = *(const float2*)(hp1 + s * 16 + cb + 8);
    }

#pragma unroll 2
    for (int ks = 0; ks < 16; ks++) {
        uint32_t ah[4], al[4];
#pragma unroll
        for (int j = 0; j < 4; j++)
            split_pack(pA[ks & 1][j].x, pA[ks & 1][j].y, ah[j], al[j]);
        if (ks < 14) {
            int s = ks & 1;
#pragma unroll
            for (int j = 0; j < 4; j++) {
                const float* base = (j & 1) ? hp1 : hp0;
                pA[s][j] = *(const float2*)(base + (ks + 2) * 16 + cb + (j >> 1) * 8);
            }
        }
        const uint32_t* bfh = bf + ks * 640 + lane * 2;
        const uint32_t* bfl = bfh + 10240;
#pragma unroll
        for (int nt = 0; nt < 10; nt++) {
            uint2 bh = *(const uint2*)(bfh + nt * 64);
            uint2 bl = *(const uint2*)(bfl + nt * 64);
            mma16816(c[nt], ah, bh.x, bh.y);
            mma16816(c[nt], ah, bl.x, bl.y);
            mma16816(c[nt], al, bh.x, bh.y);
        }
    }

    {
        float4 x0 = xs[wid * 16 + g];
        float4 x1 = xs[wid * 16 + g + 8];
#pragma unroll
        for (int nt = 0; nt < 10; nt++) {
#pragma unroll
            for (int sub = 0; sub < 2; sub++) {
                float e0 = expf(c[nt][sub]);
                float e1 = expf(c[nt][2 + sub]);
                float v0 = e0 + e1;
                float v1 = e0 * x0.x + e1 * x1.x;
                float v2 = e0 * x0.y + e1 * x1.y;
                float v3 = e0 * x0.z + e1 * x1.z;
#pragma unroll
                for (int d = 16; d >= 4; d >>= 1) {
                    v0 += __shfl_down_sync(0xffffffffu, v0, d);
                    v1 += __shfl_down_sync(0xffffffffu, v1, d);
                    v2 += __shfl_down_sync(0xffffffffu, v2, d);
                    v3 += __shfl_down_sync(0xffffffffu, v3, d);
                }
                if (lane < 4) {
                    int cc = nt * 8 + 2 * lane + sub;
                    float* rp = red + wid * 320 + cc * 4;
                    rp[0] = v0; rp[1] = v1; rp[2] = v2; rp[3] = v3;
                }
            }
        }
    }
    __syncthreads();
    for (int v = tid; v < 320; v += 512) {
        float sum = 0.f;
#pragma unroll
        for (int w2 = 0; w2 < 16; w2++) sum += red[w2 * 320 + v];
        atomicAdd(&g_S[b * 320 + v], sum);
    }
}

// ---------------- tail: 2 keypoints per 1024-thread block, 512 threads/kp ----------------
// 80 blocks; per-kp scan = 8 pts/thread (2 passes), 9-stage merge tree over 512.
#define PAD 9
#define TAIL_SD   0                              // float[2][512*9]
#define TAIL_SI   (2 * 512 * PAD * 4)            // int[2][512*9]
#define TAIL_HM   (TAIL_SI + 2 * 512 * PAD * 4)  // float[2][256]
#define TAIL_SMEM (TAIL_HM + 2 * 256 * 4)        // 75776
__global__ void __launch_bounds__(1024) k_tail(const float* __restrict__ x_rec,
                                               const float* __restrict__ h_rec,
                                               const float* __restrict__ W_mlp,
                                               const float* __restrict__ b_mlp,
                                               const float* __restrict__ gamma,
                                               const float* __restrict__ beta,
                                               float* __restrict__ out) {
    extern __shared__ char smt[];
    float* sdp = (float*)(smt + TAIL_SD);
    int*   sip = (int*)(smt + TAIL_SI);
    float* hmp = (float*)(smt + TAIL_HM);
    __shared__ float kpos[2][4];
    __shared__ float dk8[2][KNN];
    __shared__ int   id8[2][KNN];
    __shared__ float rbuf[2][16];
    __shared__ float mv[2][2];

    int half = threadIdx.x >> 9;
    int t = threadIdx.x & 511;
    int bk = blockIdx.x * 2 + half;
    int b = bk / NK;
    float* sd = sdp + half * 512 * PAD;
    int*   si = sip + half * 512 * PAD;
    float* hm = hmp + half * 256;

    if (t == 0) {
        float p0 = 0.f, p1 = 0.f, p2 = 0.f;
#pragma unroll
        for (int h = 0; h < HH; h++) {
            const float* S = g_S + bk * 16 + h * 4;
            float inv = 1.f / S[0];
            p0 += S[1] * inv; p1 += S[2] * inv; p2 += S[3] * inv;
        }
        p0 *= 0.25f; p1 *= 0.25f; p2 *= 0.25f;
        kpos[half][0] = p0; kpos[half][1] = p1; kpos[half][2] = p2;
        out[bk * 3 + 0] = p0; out[bk * 3 + 1] = p1; out[bk * 3 + 2] = p2;
    }
    __syncthreads();
    float px = kpos[half][0], py = kpos[half][1], pz = kpos[half][2];

    // register-resident top-8; 8 points/thread in 2 batched passes
    float bd[KNN]; int bi[KNN];
#pragma unroll
    for (int j = 0; j < KNN; j++) { bd[j] = 3.4e38f; bi[j] = 0x7fffffff; }
    const float* xb = x_rec + (size_t)b * NR * 3;
#pragma unroll 1
    for (int base = 0; base < NR; base += 2048) {
        float d2v[4];
#pragma unroll
        for (int u = 0; u < 4; u++) {
            int r = base + u * 512 + t;
            float dx = xb[r * 3 + 0] - px;
            float dy = xb[r * 3 + 1] - py;
            float dz = xb[r * 3 + 2] - pz;
            d2v[u] = dx * dx + dy * dy + dz * dz;
        }
#pragma unroll
        for (int u = 0; u < 4; u++) {
            float d2 = d2v[u];
            if (d2 < bd[KNN - 1]) {
                bd[KNN - 1] = d2;
                bi[KNN - 1] = base + u * 512 + t;
#pragma unroll
                for (int j = KNN - 1; j >= 1; j--) {
                    bool sw = bd[j] < bd[j - 1];
                    float td = sw ? bd[j - 1] : bd[j];
                    float th = sw ? bd[j] : bd[j - 1];
                    int   ti = sw ? bi[j - 1] : bi[j];
                    int   th2 = sw ? bi[j] : bi[j - 1];
                    bd[j] = td; bd[j - 1] = th;
                    bi[j] = ti; bi[j - 1] = th2;
                }
            }
        }
    }
#pragma unroll
    for (int j = 0; j < KNN; j++) { sd[t * PAD + j] = bd[j]; si[t * PAD + j] = bi[j]; }
    for (int stride = 256; stride >= 1; stride >>= 1) {
        __syncthreads();
        if (t < stride) {
            float od[KNN]; int oi[KNN];
            int ia = 0, ib = 0;
#pragma unroll
            for (int o = 0; o < KNN; o++) {
                float da = sd[t * PAD + ia], db = sd[(t + stride) * PAD + ib];
                int xa = si[t * PAD + ia], xb2 = si[(t + stride) * PAD + ib];
                bool ta = (da < db) || (da == db && xa < xb2);
                if (ta) { od[o] = da; oi[o] = xa; ia++; }
                else    { od[o] = db; oi[o] = xb2; ib++; }
            }
#pragma unroll
            for (int o = 0; o < KNN; o++) { sd[t * PAD + o] = od[o]; si[t * PAD + o] = oi[o]; }
        }
    }
    __syncthreads();
    if (t < KNN) { dk8[half][t] = sqrtf(sd[t]); id8[half][t] = si[t]; }
    __syncthreads();

    if (t < 256) {
        int j = t;
        float a = 0.f;
#pragma unroll
        for (int tt = 0; tt < KNN; tt++)
            a += h_rec[((size_t)b * NR + id8[half][tt]) * FF + j];
        hm[j] = a * 0.125f;
    }
    __syncthreads();

    float y = 0.f;
    if (t < 256) {
        int j = t;
        y = b_mlp[j];
#pragma unroll 16
        for (int i = 0; i < FF; i++) y += hm[i] * W_mlp[i * FF + j];
#pragma unroll
        for (int tt = 0; tt < KNN; tt++) y += dk8[half][tt] * W_mlp[(FF + tt) * FF + j];
        y = y / (1.f + expf(-y));

        float s1 = y, s2 = y * y;
#pragma unroll
        for (int d = 16; d; d >>= 1) {
            s1 += __shfl_down_sync(0xffffffffu, s1, d);
            s2 += __shfl_down_sync(0xffffffffu, s2, d);
        }
        int lane = t & 31, w = t >> 5;
        if (lane == 0) { rbuf[half][w] = s1; rbuf[half][8 + w] = s2; }
    }
    __syncthreads();
    if (t == 0) {
        float sa = 0.f, sb = 0.f;
#pragma unroll
        for (int w2 = 0; w2 < 8; w2++) { sa += rbuf[half][w2]; sb += rbuf[half][8 + w2]; }
        float mu = sa * (1.f / 256.f);
        mv[half][0] = mu;
        mv[half][1] = sb * (1.f / 256.f) - mu * mu;
    }
    __syncthreads();
    if (t < 256) {
        int j = t;
        float mu = mv[half][0];
        float inv = rsqrtf(mv[half][1] + 1e-5f);
        out[BB * NK * 3 + bk * FF + j] = (y - mu) * inv * gamma[j] + beta[j];
    }
}

// ---------------- launch ----------------
extern "C" void kernel_launch(void* const* d_in, const int* in_sizes, int n_in,
                              void* d_out, int out_size) {
    const float* h_rec = (const float*)d_in[0];
    const float* x_rec = (const float*)d_in[1];
    const float* h0_kp = (const float*)d_in[2];
    const float* W_src = (const float*)d_in[3];
    const float* W_mlp = (const float*)d_in[4];
    const float* b_mlp = (const float*)d_in[5];
    const float* gamma = (const float*)d_in[6];
    const float* beta  = (const float*)d_in[7];
    float* out = (float*)d_out;

    const int v_smem = V_SMEM_FLOATS * 4;
    const int ft_smem = FT_SMEM_FLOATS * 4;
    cudaFuncSetAttribute(k_attn, cudaFuncAttributeMaxDynamicSharedMemorySize, ATTN_SMEM_BYTES);
    cudaFuncSetAttribute(k_V, cudaFuncAttributeMaxDynamicSharedMemorySize, v_smem);
    cudaFuncSetAttribute(k_ftdst, cudaFuncAttributeMaxDynamicSharedMemorySize, ft_smem);
    cudaFuncSetAttribute(k_tail, cudaFuncAttributeMaxDynamicSharedMemorySize, TAIL_SMEM);

    k_ftdst<<<dim3(16, BB), 256, ft_smem>>>(h0_kp, W_src);        // launch 1 (+zero g_V,g_S)
    k_V<<<dim3(16, BB), 256, v_smem>>>(W_src);                    // launch 2
    k_attn<<<dim3(16, BB), 512, ATTN_SMEM_BYTES>>>(h_rec, x_rec); // launch 3
    k_tail<<<BB * NK / 2, 1024, TAIL_SMEM>>>(x_rec, h_rec, W_mlp, b_mlp, gamma, beta, out);  // launch 4 -> profiled
}